// round 16
// baseline (speedup 1.0000x reference)
#include <cuda_runtime.h>
#include <cuda_fp16.h>

#define NB 4
#define NS 2048
#define ND 1024
#define NH 16
#define HD 64
#define NEGV (-10000.0f)
#define SCALE 0.125f

// ---------------- scratch (static device arrays; no runtime allocation) ------------
__device__ __half g_qh2[NB * NH * NS * HD];   // [bh][s][d] fp16
__device__ __half g_kh2[NB * NH * NS * HD];   // [bh][s][d] fp16
__device__ __half g_vh2[NB * NH * HD * NS];   // [bh][d][s] fp16 (transposed)
__device__ float  g_ao [NB * NS * ND];        // attention output pre-LN
__device__ float  g_sc_fb[NB * NH * NS * NS]; // score scratch if attn output absent
__device__ float2 g_rst[NB * NH * NS];        // per-row (max, 1/sum)

// ---------------- helpers ----------------------------------------------------------
__device__ __forceinline__ unsigned packh2(float x, float y) {
    __half2 h = __floats2half2_rn(x, y);
    return *reinterpret_cast<unsigned*>(&h);
}
__device__ __forceinline__ void cp16g(void* dst_smem, const void* src) {
    unsigned d = (unsigned)__cvta_generic_to_shared(dst_smem);
    asm volatile("cp.async.cg.shared.global [%0], [%1], 16;" :: "r"(d), "l"(src));
}
__device__ __forceinline__ void cp_commit()  { asm volatile("cp.async.commit_group;" ::: "memory"); }
__device__ __forceinline__ void cp_wait0()   { asm volatile("cp.async.wait_group 0;" ::: "memory"); }

__device__ __forceinline__ void mma_f16(float c[4], const unsigned a[4], const unsigned b[2]) {
    asm volatile(
        "mma.sync.aligned.m16n8k16.row.col.f32.f16.f16.f32 "
        "{%0,%1,%2,%3}, {%4,%5,%6,%7}, {%8,%9}, {%0,%1,%2,%3};"
        : "+f"(c[0]), "+f"(c[1]), "+f"(c[2]), "+f"(c[3])
        : "r"(a[0]), "r"(a[1]), "r"(a[2]), "r"(a[3]), "r"(b[0]), "r"(b[1]));
}

// ---------------- QKV projection: Y = X @ W^T + b (fp16 m16n8k16) ------------------
// CTA 128x128, BK=16, 256 thr = 8 warps, warp tile 64x32; double-buffered fp16 smem.
// which 0/1 -> fp16 [bh][s][d]; which 2 -> fp16 transposed [bh][d][s].
__global__ __launch_bounds__(256) void proj_kernel(
    const float* __restrict__ X, const float* __restrict__ W,
    const float* __restrict__ bias, int which)
{
    __shared__ __align__(16) unsigned Asw[2][128 * 12];
    __shared__ __align__(16) unsigned Bsw[2][128 * 12];

    const int t = threadIdx.x;
    const int lane = t & 31, w = t >> 5;
    const int g = lane >> 2, tg = lane & 3;
    const int m0 = blockIdx.x * 128;
    const int n0 = blockIdx.y * 128;
    const int wm = (w & 1) * 64;
    const int wn = (w >> 1) * 32;

    float acc[4][4][4];
#pragma unroll
    for (int mt = 0; mt < 4; mt++)
#pragma unroll
        for (int nt = 0; nt < 4; nt++)
#pragma unroll
            for (int r = 0; r < 4; r++) acc[mt][nt][r] = 0.0f;

    int stage = 0;
    for (int k0 = 0; k0 < ND; k0 += 16, stage ^= 1) {
#pragma unroll
        for (int r = 0; r < 2; r++) {
            const int idx = t + 256 * r;
            const int row = idx >> 2, qc = (idx & 3) * 4;
            float4 av = *(const float4*)(X + (size_t)(m0 + row) * ND + k0 + qc);
            *(uint2*)&Asw[stage][row * 12 + qc / 2] =
                make_uint2(packh2(av.x, av.y), packh2(av.z, av.w));
            float4 bv = *(const float4*)(W + (size_t)(n0 + row) * ND + k0 + qc);
            *(uint2*)&Bsw[stage][row * 12 + qc / 2] =
                make_uint2(packh2(bv.x, bv.y), packh2(bv.z, bv.w));
        }
        __syncthreads();   // single barrier/iter (skewed double buffer)
        unsigned a[4][4], b[4][2];
#pragma unroll
        for (int mt = 0; mt < 4; mt++) {
            const int m = wm + mt * 16 + g;
            a[mt][0] = Asw[stage][m * 12 + tg];
            a[mt][1] = Asw[stage][(m + 8) * 12 + tg];
            a[mt][2] = Asw[stage][m * 12 + tg + 4];
            a[mt][3] = Asw[stage][(m + 8) * 12 + tg + 4];
        }
#pragma unroll
        for (int nt = 0; nt < 4; nt++) {
            const int n = wn + nt * 8 + g;
            b[nt][0] = Bsw[stage][n * 12 + tg];
            b[nt][1] = Bsw[stage][n * 12 + tg + 4];
        }
#pragma unroll
        for (int mt = 0; mt < 4; mt++)
#pragma unroll
            for (int nt = 0; nt < 4; nt++)
                mma_f16(acc[mt][nt], a[mt], b[nt]);
    }

    __half* outQK = (which == 0) ? g_qh2 : g_kh2;
#pragma unroll
    for (int mt = 0; mt < 4; mt++) {
#pragma unroll
        for (int rr = 0; rr < 2; rr++) {
            const int row = m0 + wm + mt * 16 + g + rr * 8;
            const int b_ = row / NS, s = row % NS;
#pragma unroll
            for (int nt = 0; nt < 4; nt++) {
                const int col = n0 + wn + nt * 8 + tg * 2;
                const int h = col >> 6, d = col & 63;
                const float vx = acc[mt][nt][rr * 2 + 0] + bias[col];
                const float vy = acc[mt][nt][rr * 2 + 1] + bias[col + 1];
                const size_t bh = (size_t)(b_ * NH + h);
                if (which == 2) {
                    g_vh2[(bh * HD + d)     * NS + s] = __float2half_rn(vx);
                    g_vh2[(bh * HD + d + 1) * NS + s] = __float2half_rn(vy);
                } else {
                    __half2 hv = __floats2half2_rn(vx, vy);
                    *(__half2*)&outQK[(bh * NS + s) * HD + d] = hv;
                }
            }
        }
    }
}

// ---------------- QK^T GEMM + scale + masks -> masked scores -----------------------
// grid (32 q-tiles, 16 k-tiles, 64 bh); 256 thr; CTA 64(M)x128(N), warp tile 32x32.
// Small tile -> ~90 regs -> 2-3 CTAs/SM (fixes the regs=130 -> 1 CTA/SM stall).
__global__ __launch_bounds__(256) void qk_kernel(const int* __restrict__ mask,
                                                 float* __restrict__ sc_arg)
{
    __shared__ __align__(16) unsigned Qs[64 * 36];    //  9216 B
    __shared__ __align__(16) unsigned Ks[128 * 36];   // 18432 B
    float* sc = sc_arg ? sc_arg : g_sc_fb;

    const int t = threadIdx.x;
    const int lane = t & 31, w = t >> 5;
    const int g = lane >> 2, tg = lane & 3;
    const int m0 = blockIdx.x * 64;
    const int n0 = blockIdx.y * 128;
    const int bh = blockIdx.z;
    const int b  = bh >> 4;
    const int wm = (w & 1) * 32;
    const int wn = (w >> 1) * 32;

    const __half* qb = g_qh2 + ((size_t)bh * NS + m0) * HD;
    const __half* kb = g_kh2 + ((size_t)bh * NS + n0) * HD;

    // stage tiles via cp.async (fp16, pre-packed pairs)
#pragma unroll
    for (int r = 0; r < 2; r++) {
        const int idx = t + 256 * r;
        const int row = idx >> 3, c = idx & 7;
        cp16g(&Qs[row * 36 + c * 4], qb + (size_t)row * HD + c * 8);
    }
#pragma unroll
    for (int r = 0; r < 4; r++) {
        const int idx = t + 256 * r;
        const int row = idx >> 3, c = idx & 7;
        cp16g(&Ks[row * 36 + c * 4], kb + (size_t)row * HD + c * 8);
    }
    cp_commit(); cp_wait0();
    __syncthreads();

    float acc[2][4][4];
#pragma unroll
    for (int mt = 0; mt < 2; mt++)
#pragma unroll
        for (int nt = 0; nt < 4; nt++)
#pragma unroll
            for (int r = 0; r < 4; r++) acc[mt][nt][r] = 0.0f;

#pragma unroll
    for (int ks = 0; ks < 4; ks++) {
        unsigned a[2][4], bb[4][2];
#pragma unroll
        for (int mt = 0; mt < 2; mt++) {
            const int m = wm + mt * 16 + g;
            a[mt][0] = Qs[m * 36 + ks * 8 + tg];
            a[mt][1] = Qs[(m + 8) * 36 + ks * 8 + tg];
            a[mt][2] = Qs[m * 36 + ks * 8 + tg + 4];
            a[mt][3] = Qs[(m + 8) * 36 + ks * 8 + tg + 4];
        }
#pragma unroll
        for (int nt = 0; nt < 4; nt++) {
            const int n = wn + nt * 8 + g;
            bb[nt][0] = Ks[n * 36 + ks * 8 + tg];
            bb[nt][1] = Ks[n * 36 + ks * 8 + tg + 4];
        }
#pragma unroll
        for (int mt = 0; mt < 2; mt++)
#pragma unroll
            for (int nt = 0; nt < 4; nt++)
                mma_f16(acc[mt][nt], a[mt], bb[nt]);
    }

    // epilogue: scale + padding mask + causal mask, write masked scores
#pragma unroll
    for (int mt = 0; mt < 2; mt++) {
#pragma unroll
        for (int rr = 0; rr < 2; rr++) {
            const int qrow = m0 + wm + mt * 16 + g + rr * 8;
            const int* mrow = mask + ((size_t)b * NS + qrow) * NS;
            float* srow = sc + ((size_t)bh * NS + qrow) * NS;
#pragma unroll
            for (int nt = 0; nt < 4; nt++) {
                const int col = n0 + wn + nt * 8 + tg * 2;
                int2 mv = *(const int2*)(mrow + col);
                float sx = acc[mt][nt][rr * 2 + 0] * SCALE
                         + (1.0f - (float)mv.x) * NEGV + ((col     > qrow) ? NEGV : 0.0f);
                float sy = acc[mt][nt][rr * 2 + 1] * SCALE
                         + (1.0f - (float)mv.y) * NEGV + ((col + 1 > qrow) ? NEGV : 0.0f);
                *(float2*)(srow + col) = make_float2(sx, sy);
            }
        }
    }
}

// ---------------- row stats (read-only): per row (max, 1/sum-of-exp) ---------------
__global__ __launch_bounds__(256) void rs_kernel(const float* __restrict__ sc_arg)
{
    const float* sc = sc_arg ? sc_arg : g_sc_fb;
    const int lane = threadIdx.x & 31;
    const size_t row = (size_t)blockIdx.x * 8 + (threadIdx.x >> 5);
    const float* p = sc + row * NS;

    float4 v[16];
    float mx = -3.0e38f;
#pragma unroll
    for (int j = 0; j < 16; j++) {
        v[j] = *(const float4*)(p + j * 128 + lane * 4);
        mx = fmaxf(mx, fmaxf(fmaxf(v[j].x, v[j].y), fmaxf(v[j].z, v[j].w)));
    }
#pragma unroll
    for (int o = 16; o > 0; o >>= 1) mx = fmaxf(mx, __shfl_xor_sync(0xffffffffu, mx, o));
    float sum = 0.0f;
#pragma unroll
    for (int j = 0; j < 16; j++) {
        sum += (__expf(v[j].x - mx) + __expf(v[j].y - mx))
             + (__expf(v[j].z - mx) + __expf(v[j].w - mx));
    }
#pragma unroll
    for (int o = 16; o > 0; o >>= 1) sum += __shfl_xor_sync(0xffffffffu, sum, o);
    if (lane == 0) g_rst[row] = make_float2(mx, 1.0f / sum);
}

// ---------------- PV GEMM (+ exp-normalize + attn write fused into staging) --------
// grid (16 m-tiles, 64 bh); 256 thr; CTA 128(M)x64(N), K-chunks 64, double-buffered.
#define PV_PW (128 * 36)
#define PV_VW (64 * 36)
#define PV_SMEM ((2 * PV_PW + 2 * PV_VW) * 4)   // 55,296 B

__global__ __launch_bounds__(256) void pv_kernel(float* __restrict__ sc_arg)
{
    extern __shared__ __align__(16) unsigned pvs[];
    unsigned* Pw = pvs;
    unsigned* Vw = pvs + 2 * PV_PW;
    __shared__ float2 rst[128];
    float* sc = sc_arg ? sc_arg : g_sc_fb;

    const int t = threadIdx.x;
    const int lane = t & 31, w = t >> 5;
    const int g = lane >> 2, tg = lane & 3;
    const int m0 = blockIdx.x * 128;
    const int bh = blockIdx.y;
    const int b  = bh >> 4, h = bh & 15;
    const int wm = (w & 3) * 32;
    const int wn = (w >> 2) * 32;

    float*        pb = sc + ((size_t)bh * NS + m0) * NS;
    const __half* vb = g_vh2 + (size_t)bh * HD * NS;

    if (t < 128) rst[t] = g_rst[(size_t)bh * NS + m0 + t];
    __syncthreads();

    float acc[2][4][4];
#pragma unroll
    for (int mt = 0; mt < 2; mt++)
#pragma unroll
        for (int nt = 0; nt < 4; nt++)
#pragma unroll
            for (int r = 0; r < 4; r++) acc[mt][nt][r] = 0.0f;

    int stage = 0;
    for (int k0 = 0; k0 < NS; k0 += 64, stage ^= 1) {
        unsigned* Pc = Pw + stage * PV_PW;
        unsigned* Vc = Vw + stage * PV_VW;
        // stage P: read raw scores, exp-normalize, write attn probs, pack fp16
#pragma unroll
        for (int r = 0; r < 8; r++) {
            const int idx = t + 256 * r;
            const int row = idx >> 4, c4 = idx & 15;
            float* src = pb + (size_t)row * NS + k0 + c4 * 4;
            float4 p4 = *(const float4*)src;
            const float2 st = rst[row];
            p4.x = __expf(p4.x - st.x) * st.y;
            p4.y = __expf(p4.y - st.x) * st.y;
            p4.z = __expf(p4.z - st.x) * st.y;
            p4.w = __expf(p4.w - st.x) * st.y;
            *(float4*)src = p4;   // normalized attention probabilities (output)
            *(uint2*)&Pc[row * 36 + c4 * 2] =
                make_uint2(packh2(p4.x, p4.y), packh2(p4.z, p4.w));
        }
        // stage V [64 d x 64 k] fp16 transposed-global via cp.async
#pragma unroll
        for (int r = 0; r < 2; r++) {
            const int idx = t + 256 * r;
            const int d = idx >> 3, c = idx & 7;
            cp16g(&Vc[d * 36 + c * 4], vb + (size_t)d * NS + k0 + c * 8);
        }
        cp_commit(); cp_wait0();
        __syncthreads();   // single barrier/iter (skewed double buffer)
#pragma unroll
        for (int ks = 0; ks < 4; ks++) {
            unsigned a[2][4], bb[4][2];
#pragma unroll
            for (int mt = 0; mt < 2; mt++) {
                const int m = wm + mt * 16 + g;
                a[mt][0] = Pc[m * 36 + ks * 8 + tg];
                a[mt][1] = Pc[(m + 8) * 36 + ks * 8 + tg];
                a[mt][2] = Pc[m * 36 + ks * 8 + tg + 4];
                a[mt][3] = Pc[(m + 8) * 36 + ks * 8 + tg + 4];
            }
#pragma unroll
            for (int nt = 0; nt < 4; nt++) {
                const int n = wn + nt * 8 + g;
                bb[nt][0] = Vc[n * 36 + ks * 8 + tg];
                bb[nt][1] = Vc[n * 36 + ks * 8 + tg + 4];
            }
#pragma unroll
            for (int mt = 0; mt < 2; mt++)
#pragma unroll
                for (int nt = 0; nt < 4; nt++)
                    mma_f16(acc[mt][nt], a[mt], bb[nt]);
        }
    }

#pragma unroll
    for (int mt = 0; mt < 2; mt++) {
#pragma unroll
        for (int rr = 0; rr < 2; rr++) {
            const int q = m0 + wm + mt * 16 + g + rr * 8;
#pragma unroll
            for (int nt = 0; nt < 4; nt++) {
                const int d = wn + nt * 8 + tg * 2;
                float2 val = make_float2(acc[mt][nt][rr * 2 + 0], acc[mt][nt][rr * 2 + 1]);
                *(float2*)&g_ao[((size_t)b * NS + q) * ND + h * HD + d] = val;
            }
        }
    }
}

// ---------------- residual + LayerNorm, one block per (b,s) row --------------------
__global__ __launch_bounds__(256) void ln_kernel(const float* __restrict__ resid,
                                                 const float* __restrict__ gam,
                                                 const float* __restrict__ bet,
                                                 float* __restrict__ out)
{
    __shared__ float xb[ND];
    __shared__ float red[8];
    const int r = blockIdx.x;
    const int t = threadIdx.x;
    const int lane = t & 31, w = t >> 5;
    const size_t base = (size_t)r * ND;

    float lsum = 0.0f;
    for (int j = t; j < ND; j += 256) {
        const float x = g_ao[base + j] + resid[base + j];
        xb[j] = x;
        lsum += x;
    }
#pragma unroll
    for (int o = 16; o > 0; o >>= 1) lsum += __shfl_xor_sync(0xffffffffu, lsum, o);
    if (lane == 0) red[w] = lsum;
    __syncthreads();
    float tot = 0.0f;
#pragma unroll
    for (int w2 = 0; w2 < 8; w2++) tot += red[w2];
    const float mu = tot * (1.0f / ND);
    __syncthreads();

    float lv = 0.0f;
    for (int j = t; j < ND; j += 256) {
        const float dd = xb[j] - mu;
        lv += dd * dd;
    }
#pragma unroll
    for (int o = 16; o > 0; o >>= 1) lv += __shfl_xor_sync(0xffffffffu, lv, o);
    if (lane == 0) red[w] = lv;
    __syncthreads();
    float vtot = 0.0f;
#pragma unroll
    for (int w2 = 0; w2 < 8; w2++) vtot += red[w2];
    const float rstd = rsqrtf(vtot * (1.0f / ND) + 1e-5f);

    for (int j = t; j < ND; j += 256)
        out[base + j] = (xb[j] - mu) * rstd * gam[j] + bet[j];
}

// ---------------- launch -----------------------------------------------------------
extern "C" void kernel_launch(void* const* d_in, const int* in_sizes, int n_in,
                              void* d_out, int out_size)
{
    const float* q    = (const float*)d_in[0];
    const float* k    = (const float*)d_in[1];
    const float* v    = (const float*)d_in[2];
    const int*   mask = (const int*)  d_in[3];
    const float* Wq   = (const float*)d_in[4];
    const float* bq   = (const float*)d_in[5];
    const float* Wk   = (const float*)d_in[6];
    const float* bk   = (const float*)d_in[7];
    const float* Wv   = (const float*)d_in[8];
    const float* bv   = (const float*)d_in[9];
    const float* ln_g = (const float*)d_in[10];
    const float* ln_b = (const float*)d_in[11];
    float* out = (float*)d_out;

    cudaFuncSetAttribute(pv_kernel, cudaFuncAttributeMaxDynamicSharedMemorySize, PV_SMEM);

    dim3 pg(64, 8);
    proj_kernel<<<pg, 256>>>(q, Wq, bq, 0);
    proj_kernel<<<pg, 256>>>(k, Wk, bk, 1);
    proj_kernel<<<pg, 256>>>(v, Wv, bv, 2);

    float* attn = nullptr;
    const long long need = (long long)NB * NS * ND + (long long)NB * NH * NS * NS;
    if ((long long)out_size >= need) attn = out + (size_t)NB * NS * ND;

    qk_kernel<<<dim3(NS / 64, NS / 128, NB * NH), 256>>>(mask, attn);
    rs_kernel<<<(NB * NH * NS) / 8, 256>>>(attn);
    pv_kernel<<<dim3(NS / 128, NB * NH), 256, PV_SMEM>>>(attn);
    ln_kernel<<<NB * NS, 256>>>(q, ln_g, ln_b, out);
}

// round 17
// speedup vs baseline: 1.1731x; 1.1731x over previous
#include <cuda_runtime.h>
#include <cuda_fp16.h>

#define NB 4
#define NS 2048
#define ND 1024
#define NH 16
#define HD 64
#define NEGV (-10000.0f)
#define SCALE 0.125f

// ---------------- scratch (static device arrays; no runtime allocation) ------------
__device__ __half g_qh2[NB * NH * NS * HD];   // [bh][s][d] fp16
__device__ __half g_kh2[NB * NH * NS * HD];   // [bh][s][d] fp16
__device__ __half g_vh2[NB * NH * HD * NS];   // [bh][d][s] fp16 (transposed)
__device__ float  g_ao [NB * NS * ND];        // attention output pre-LN
__device__ float  g_sc_fb[NB * NH * NS * NS]; // score scratch if attn output absent

// ---------------- helpers ----------------------------------------------------------
__device__ __forceinline__ unsigned packh2(float x, float y) {
    __half2 h = __floats2half2_rn(x, y);
    return *reinterpret_cast<unsigned*>(&h);
}
__device__ __forceinline__ void cp16g(void* dst_smem, const void* src) {
    unsigned d = (unsigned)__cvta_generic_to_shared(dst_smem);
    asm volatile("cp.async.cg.shared.global [%0], [%1], 16;" :: "r"(d), "l"(src));
}
__device__ __forceinline__ void cp_commit()  { asm volatile("cp.async.commit_group;" ::: "memory"); }
__device__ __forceinline__ void cp_wait0()   { asm volatile("cp.async.wait_group 0;" ::: "memory"); }

__device__ __forceinline__ void mma_f16(float c[4], const unsigned a[4], const unsigned b[2]) {
    asm volatile(
        "mma.sync.aligned.m16n8k16.row.col.f32.f16.f16.f32 "
        "{%0,%1,%2,%3}, {%4,%5,%6,%7}, {%8,%9}, {%0,%1,%2,%3};"
        : "+f"(c[0]), "+f"(c[1]), "+f"(c[2]), "+f"(c[3])
        : "r"(a[0]), "r"(a[1]), "r"(a[2]), "r"(a[3]), "r"(b[0]), "r"(b[1]));
}

// ---------------- QKV projection: Y = X @ W^T + b (fp16 m16n8k16) ------------------
// CTA 128x128, BK=16, 256 thr = 8 warps, warp tile 64x32; double-buffered fp16 smem.
// which 0/1 -> fp16 [bh][s][d]; which 2 -> fp16 transposed [bh][d][s].
__global__ __launch_bounds__(256) void proj_kernel(
    const float* __restrict__ X, const float* __restrict__ W,
    const float* __restrict__ bias, int which)
{
    __shared__ __align__(16) unsigned Asw[2][128 * 12];
    __shared__ __align__(16) unsigned Bsw[2][128 * 12];

    const int t = threadIdx.x;
    const int lane = t & 31, w = t >> 5;
    const int g = lane >> 2, tg = lane & 3;
    const int m0 = blockIdx.x * 128;
    const int n0 = blockIdx.y * 128;
    const int wm = (w & 1) * 64;
    const int wn = (w >> 1) * 32;

    float acc[4][4][4];
#pragma unroll
    for (int mt = 0; mt < 4; mt++)
#pragma unroll
        for (int nt = 0; nt < 4; nt++)
#pragma unroll
            for (int r = 0; r < 4; r++) acc[mt][nt][r] = 0.0f;

    int stage = 0;
    for (int k0 = 0; k0 < ND; k0 += 16, stage ^= 1) {
#pragma unroll
        for (int r = 0; r < 2; r++) {
            const int idx = t + 256 * r;
            const int row = idx >> 2, qc = (idx & 3) * 4;
            float4 av = *(const float4*)(X + (size_t)(m0 + row) * ND + k0 + qc);
            *(uint2*)&Asw[stage][row * 12 + qc / 2] =
                make_uint2(packh2(av.x, av.y), packh2(av.z, av.w));
            float4 bv = *(const float4*)(W + (size_t)(n0 + row) * ND + k0 + qc);
            *(uint2*)&Bsw[stage][row * 12 + qc / 2] =
                make_uint2(packh2(bv.x, bv.y), packh2(bv.z, bv.w));
        }
        __syncthreads();   // single barrier/iter (skewed double buffer)
        unsigned a[4][4], b[4][2];
#pragma unroll
        for (int mt = 0; mt < 4; mt++) {
            const int m = wm + mt * 16 + g;
            a[mt][0] = Asw[stage][m * 12 + tg];
            a[mt][1] = Asw[stage][(m + 8) * 12 + tg];
            a[mt][2] = Asw[stage][m * 12 + tg + 4];
            a[mt][3] = Asw[stage][(m + 8) * 12 + tg + 4];
        }
#pragma unroll
        for (int nt = 0; nt < 4; nt++) {
            const int n = wn + nt * 8 + g;
            b[nt][0] = Bsw[stage][n * 12 + tg];
            b[nt][1] = Bsw[stage][n * 12 + tg + 4];
        }
#pragma unroll
        for (int mt = 0; mt < 4; mt++)
#pragma unroll
            for (int nt = 0; nt < 4; nt++)
                mma_f16(acc[mt][nt], a[mt], b[nt]);
    }

    __half* outQK = (which == 0) ? g_qh2 : g_kh2;
#pragma unroll
    for (int mt = 0; mt < 4; mt++) {
#pragma unroll
        for (int rr = 0; rr < 2; rr++) {
            const int row = m0 + wm + mt * 16 + g + rr * 8;
            const int b_ = row / NS, s = row % NS;
#pragma unroll
            for (int nt = 0; nt < 4; nt++) {
                const int col = n0 + wn + nt * 8 + tg * 2;
                const int h = col >> 6, d = col & 63;
                const float vx = acc[mt][nt][rr * 2 + 0] + bias[col];
                const float vy = acc[mt][nt][rr * 2 + 1] + bias[col + 1];
                const size_t bh = (size_t)(b_ * NH + h);
                if (which == 2) {
                    g_vh2[(bh * HD + d)     * NS + s] = __float2half_rn(vx);
                    g_vh2[(bh * HD + d + 1) * NS + s] = __float2half_rn(vy);
                } else {
                    __half2 hv = __floats2half2_rn(vx, vy);
                    *(__half2*)&outQK[(bh * NS + s) * HD + d] = hv;
                }
            }
        }
    }
}

// ---------------- QK^T GEMM + scale + masks -> masked scores -----------------------
// grid (32 q-tiles, 16 k-tiles, 64 bh); 256 thr; CTA 64(M)x128(N), warp tile 32x32.
// Small tile -> 64 regs -> high occupancy (validated R16: 372us, occ 46%).
__global__ __launch_bounds__(256) void qk_kernel(const int* __restrict__ mask,
                                                 float* __restrict__ sc_arg)
{
    __shared__ __align__(16) unsigned Qs[64 * 36];    //  9216 B
    __shared__ __align__(16) unsigned Ks[128 * 36];   // 18432 B
    float* sc = sc_arg ? sc_arg : g_sc_fb;

    const int t = threadIdx.x;
    const int lane = t & 31, w = t >> 5;
    const int g = lane >> 2, tg = lane & 3;
    const int m0 = blockIdx.x * 64;
    const int n0 = blockIdx.y * 128;
    const int bh = blockIdx.z;
    const int b  = bh >> 4;
    const int wm = (w & 1) * 32;
    const int wn = (w >> 1) * 32;

    const __half* qb = g_qh2 + ((size_t)bh * NS + m0) * HD;
    const __half* kb = g_kh2 + ((size_t)bh * NS + n0) * HD;

    // stage tiles via cp.async (fp16, pre-packed pairs)
#pragma unroll
    for (int r = 0; r < 2; r++) {
        const int idx = t + 256 * r;
        const int row = idx >> 3, c = idx & 7;
        cp16g(&Qs[row * 36 + c * 4], qb + (size_t)row * HD + c * 8);
    }
#pragma unroll
    for (int r = 0; r < 4; r++) {
        const int idx = t + 256 * r;
        const int row = idx >> 3, c = idx & 7;
        cp16g(&Ks[row * 36 + c * 4], kb + (size_t)row * HD + c * 8);
    }
    cp_commit(); cp_wait0();
    __syncthreads();

    float acc[2][4][4];
#pragma unroll
    for (int mt = 0; mt < 2; mt++)
#pragma unroll
        for (int nt = 0; nt < 4; nt++)
#pragma unroll
            for (int r = 0; r < 4; r++) acc[mt][nt][r] = 0.0f;

#pragma unroll
    for (int ks = 0; ks < 4; ks++) {
        unsigned a[2][4], bb[4][2];
#pragma unroll
        for (int mt = 0; mt < 2; mt++) {
            const int m = wm + mt * 16 + g;
            a[mt][0] = Qs[m * 36 + ks * 8 + tg];
            a[mt][1] = Qs[(m + 8) * 36 + ks * 8 + tg];
            a[mt][2] = Qs[m * 36 + ks * 8 + tg + 4];
            a[mt][3] = Qs[(m + 8) * 36 + ks * 8 + tg + 4];
        }
#pragma unroll
        for (int nt = 0; nt < 4; nt++) {
            const int n = wn + nt * 8 + g;
            bb[nt][0] = Ks[n * 36 + ks * 8 + tg];
            bb[nt][1] = Ks[n * 36 + ks * 8 + tg + 4];
        }
#pragma unroll
        for (int mt = 0; mt < 2; mt++)
#pragma unroll
            for (int nt = 0; nt < 4; nt++)
                mma_f16(acc[mt][nt], a[mt], bb[nt]);
    }

    // epilogue: scale + padding mask + causal mask, write masked scores
#pragma unroll
    for (int mt = 0; mt < 2; mt++) {
#pragma unroll
        for (int rr = 0; rr < 2; rr++) {
            const int qrow = m0 + wm + mt * 16 + g + rr * 8;
            const int* mrow = mask + ((size_t)b * NS + qrow) * NS;
            float* srow = sc + ((size_t)bh * NS + qrow) * NS;
#pragma unroll
            for (int nt = 0; nt < 4; nt++) {
                const int col = n0 + wn + nt * 8 + tg * 2;
                int2 mv = *(const int2*)(mrow + col);
                float sx = acc[mt][nt][rr * 2 + 0] * SCALE
                         + (1.0f - (float)mv.x) * NEGV + ((col     > qrow) ? NEGV : 0.0f);
                float sy = acc[mt][nt][rr * 2 + 1] * SCALE
                         + (1.0f - (float)mv.y) * NEGV + ((col + 1 > qrow) ? NEGV : 0.0f);
                *(float2*)(srow + col) = make_float2(sx, sy);
            }
        }
    }
}

// ---------------- row softmax in place: one warp per 2048-row ----------------------
__global__ __launch_bounds__(256) void sm_kernel(float* __restrict__ sc_arg)
{
    float* sc = sc_arg ? sc_arg : g_sc_fb;
    const int lane = threadIdx.x & 31;
    const size_t row = (size_t)blockIdx.x * 8 + (threadIdx.x >> 5);
    float* p = sc + row * NS;

    float4 v[16];
    float mx = -3.0e38f;
#pragma unroll
    for (int j = 0; j < 16; j++) {
        v[j] = *(float4*)(p + j * 128 + lane * 4);
        mx = fmaxf(mx, fmaxf(fmaxf(v[j].x, v[j].y), fmaxf(v[j].z, v[j].w)));
    }
#pragma unroll
    for (int o = 16; o > 0; o >>= 1) mx = fmaxf(mx, __shfl_xor_sync(0xffffffffu, mx, o));
    float sum = 0.0f;
#pragma unroll
    for (int j = 0; j < 16; j++) {
        v[j].x = __expf(v[j].x - mx); v[j].y = __expf(v[j].y - mx);
        v[j].z = __expf(v[j].z - mx); v[j].w = __expf(v[j].w - mx);
        sum += (v[j].x + v[j].y) + (v[j].z + v[j].w);
    }
#pragma unroll
    for (int o = 16; o > 0; o >>= 1) sum += __shfl_xor_sync(0xffffffffu, sum, o);
    const float inv = 1.0f / sum;
#pragma unroll
    for (int j = 0; j < 16; j++) {
        v[j].x *= inv; v[j].y *= inv; v[j].z *= inv; v[j].w *= inv;
        *(float4*)(p + j * 128 + lane * 4) = v[j];
    }
}

// ---------------- PV GEMM: out = P @ V -> g_ao -------------------------------------
// grid (16 m-tiles, 64 bh); 256 thr; CTA 128(M)x64(N), K-chunks 64, double-buffered.
#define PV_PW (128 * 36)
#define PV_VW (64 * 36)
#define PV_SMEM ((2 * PV_PW + 2 * PV_VW) * 4)   // 55,296 B

__global__ __launch_bounds__(256) void pv_kernel(const float* __restrict__ sc_arg)
{
    extern __shared__ __align__(16) unsigned pvs[];
    unsigned* Pw = pvs;
    unsigned* Vw = pvs + 2 * PV_PW;
    const float* sc = sc_arg ? sc_arg : g_sc_fb;

    const int t = threadIdx.x;
    const int lane = t & 31, w = t >> 5;
    const int g = lane >> 2, tg = lane & 3;
    const int m0 = blockIdx.x * 128;
    const int bh = blockIdx.y;
    const int b  = bh >> 4, h = bh & 15;
    const int wm = (w & 3) * 32;
    const int wn = (w >> 2) * 32;

    const float*  pb = sc + ((size_t)bh * NS + m0) * NS;
    const __half* vb = g_vh2 + (size_t)bh * HD * NS;

    float acc[2][4][4];
#pragma unroll
    for (int mt = 0; mt < 2; mt++)
#pragma unroll
        for (int nt = 0; nt < 4; nt++)
#pragma unroll
            for (int r = 0; r < 4; r++) acc[mt][nt][r] = 0.0f;

    int stage = 0;
    for (int k0 = 0; k0 < NS; k0 += 64, stage ^= 1) {
        unsigned* Pc = Pw + stage * PV_PW;
        unsigned* Vc = Vw + stage * PV_VW;
        // stage P [128 x 64] fp32 -> fp16 packed
#pragma unroll
        for (int r = 0; r < 8; r++) {
            const int idx = t + 256 * r;
            const int row = idx >> 4, c4 = idx & 15;
            float4 p4 = *(const float4*)(pb + (size_t)row * NS + k0 + c4 * 4);
            *(uint2*)&Pc[row * 36 + c4 * 2] =
                make_uint2(packh2(p4.x, p4.y), packh2(p4.z, p4.w));
        }
        // stage V [64 d x 64 k] fp16 transposed-global via cp.async
#pragma unroll
        for (int r = 0; r < 2; r++) {
            const int idx = t + 256 * r;
            const int d = idx >> 3, c = idx & 7;
            cp16g(&Vc[d * 36 + c * 4], vb + (size_t)d * NS + k0 + c * 8);
        }
        cp_commit(); cp_wait0();
        __syncthreads();   // single barrier/iter (skewed double buffer)
#pragma unroll
        for (int ks = 0; ks < 4; ks++) {
            unsigned a[2][4], bb[4][2];
#pragma unroll
            for (int mt = 0; mt < 2; mt++) {
                const int m = wm + mt * 16 + g;
                a[mt][0] = Pc[m * 36 + ks * 8 + tg];
                a[mt][1] = Pc[(m + 8) * 36 + ks * 8 + tg];
                a[mt][2] = Pc[m * 36 + ks * 8 + tg + 4];
                a[mt][3] = Pc[(m + 8) * 36 + ks * 8 + tg + 4];
            }
#pragma unroll
            for (int nt = 0; nt < 4; nt++) {
                const int n = wn + nt * 8 + g;
                bb[nt][0] = Vc[n * 36 + ks * 8 + tg];
                bb[nt][1] = Vc[n * 36 + ks * 8 + tg + 4];
            }
#pragma unroll
            for (int mt = 0; mt < 2; mt++)
#pragma unroll
                for (int nt = 0; nt < 4; nt++)
                    mma_f16(acc[mt][nt], a[mt], bb[nt]);
        }
    }

#pragma unroll
    for (int mt = 0; mt < 2; mt++) {
#pragma unroll
        for (int rr = 0; rr < 2; rr++) {
            const int q = m0 + wm + mt * 16 + g + rr * 8;
#pragma unroll
            for (int nt = 0; nt < 4; nt++) {
                const int d = wn + nt * 8 + tg * 2;
                float2 val = make_float2(acc[mt][nt][rr * 2 + 0], acc[mt][nt][rr * 2 + 1]);
                *(float2*)&g_ao[((size_t)b * NS + q) * ND + h * HD + d] = val;
            }
        }
    }
}

// ---------------- residual + LayerNorm, one block per (b,s) row --------------------
__global__ __launch_bounds__(256) void ln_kernel(const float* __restrict__ resid,
                                                 const float* __restrict__ gam,
                                                 const float* __restrict__ bet,
                                                 float* __restrict__ out)
{
    __shared__ float xb[ND];
    __shared__ float red[8];
    const int r = blockIdx.x;
    const int t = threadIdx.x;
    const int lane = t & 31, w = t >> 5;
    const size_t base = (size_t)r * ND;

    float lsum = 0.0f;
    for (int j = t; j < ND; j += 256) {
        const float x = g_ao[base + j] + resid[base + j];
        xb[j] = x;
        lsum += x;
    }
#pragma unroll
    for (int o = 16; o > 0; o >>= 1) lsum += __shfl_xor_sync(0xffffffffu, lsum, o);
    if (lane == 0) red[w] = lsum;
    __syncthreads();
    float tot = 0.0f;
#pragma unroll
    for (int w2 = 0; w2 < 8; w2++) tot += red[w2];
    const float mu = tot * (1.0f / ND);
    __syncthreads();

    float lv = 0.0f;
    for (int j = t; j < ND; j += 256) {
        const float dd = xb[j] - mu;
        lv += dd * dd;
    }
#pragma unroll
    for (int o = 16; o > 0; o >>= 1) lv += __shfl_xor_sync(0xffffffffu, lv, o);
    if (lane == 0) red[w] = lv;
    __syncthreads();
    float vtot = 0.0f;
#pragma unroll
    for (int w2 = 0; w2 < 8; w2++) vtot += red[w2];
    const float rstd = rsqrtf(vtot * (1.0f / ND) + 1e-5f);

    for (int j = t; j < ND; j += 256)
        out[base + j] = (xb[j] - mu) * rstd * gam[j] + bet[j];
}

// ---------------- launch -----------------------------------------------------------
extern "C" void kernel_launch(void* const* d_in, const int* in_sizes, int n_in,
                              void* d_out, int out_size)
{
    const float* q    = (const float*)d_in[0];
    const float* k    = (const float*)d_in[1];
    const float* v    = (const float*)d_in[2];
    const int*   mask = (const int*)  d_in[3];
    const float* Wq   = (const float*)d_in[4];
    const float* bq   = (const float*)d_in[5];
    const float* Wk   = (const float*)d_in[6];
    const float* bk   = (const float*)d_in[7];
    const float* Wv   = (const float*)d_in[8];
    const float* bv   = (const float*)d_in[9];
    const float* ln_g = (const float*)d_in[10];
    const float* ln_b = (const float*)d_in[11];
    float* out = (float*)d_out;

    cudaFuncSetAttribute(pv_kernel, cudaFuncAttributeMaxDynamicSharedMemorySize, PV_SMEM);

    dim3 pg(64, 8);
    proj_kernel<<<pg, 256>>>(q, Wq, bq, 0);
    proj_kernel<<<pg, 256>>>(k, Wk, bk, 1);
    proj_kernel<<<pg, 256>>>(v, Wv, bv, 2);

    float* attn = nullptr;
    const long long need = (long long)NB * NS * ND + (long long)NB * NH * NS * NS;
    if ((long long)out_size >= need) attn = out + (size_t)NB * NS * ND;

    qk_kernel<<<dim3(NS / 64, NS / 128, NB * NH), 256>>>(mask, attn);
    sm_kernel<<<(NB * NH * NS) / 8, 256>>>(attn);
    pv_kernel<<<dim3(NS / 128, NB * NH), 256, PV_SMEM>>>(attn);
    ln_kernel<<<NB * NS, 256>>>(q, ln_g, ln_b, out);
}